// round 10
// baseline (speedup 1.0000x reference)
#include <cuda_runtime.h>
#include <cuda_bf16.h>

// 3x3 high-pass stencil: y = |0.125*(hs_top+hs_mid+hs_bot) - 1.125*center| + 1e-5
// x: (8,32,512,512) fp32, zero-padded SAME. Register-rolling, smem-free.
// Warp strip: 128 cols x 16 rows, prefetch distance 2, streaming stores.
// 42-reg cap -> 6 CTAs/SM (48 warps) for max DRAM-level parallelism.

#define W 512
#define H 512
#define ROWS 16
#define WARPS 8
#define TW 128

struct Row {
    float4 v;   // lane's 4 columns
    float  e;   // strip-edge neighbor: left on lane 0, right on lane 31
};

__device__ __forceinline__ Row load_row(const float* __restrict__ xp, int rr,
                                        int c0, int col, int lane) {
    Row o;
    o.e = 0.f;
    if ((unsigned)rr < H) {
        o.v = *reinterpret_cast<const float4*>(xp + rr * W + col);
        if (lane == 0) {
            if (c0 > 0) o.e = xp[rr * W + (c0 - 1)];
        } else if (lane == 31) {
            if (c0 + TW < W) o.e = xp[rr * W + (c0 + TW)];
        }
    } else {
        o.v = make_float4(0.f, 0.f, 0.f, 0.f);
    }
    return o;
}

__device__ __forceinline__ float4 hsum(const Row& rw, int lane) {
    float l = __shfl_up_sync(0xffffffffu, rw.v.w, 1);
    if (lane == 0) l = rw.e;
    float r = __shfl_down_sync(0xffffffffu, rw.v.x, 1);
    if (lane == 31) r = rw.e;
    float4 h;
    h.x = l      + rw.v.x + rw.v.y;
    h.y = rw.v.x + rw.v.y + rw.v.z;
    h.z = rw.v.y + rw.v.z + rw.v.w;
    h.w = rw.v.z + rw.v.w + r;
    return h;
}

__global__ __launch_bounds__(256, 6)
void highpass_kernel(const float* __restrict__ x, float* __restrict__ y) {
    const int warp = threadIdx.x >> 5;
    const int lane = threadIdx.x & 31;

    const int c0    = blockIdx.x * TW;
    const int rbase = (blockIdx.y * WARPS + warp) * ROWS;
    const int col   = c0 + lane * 4;

    const float* __restrict__ xp = x + ((size_t)blockIdx.z << 18);
    float* __restrict__ yp       = y + ((size_t)blockIdx.z << 18);

    // prime the pipeline: rows rbase-1 .. rbase+2
    Row rm  = load_row(xp, rbase - 1, c0, col, lane);
    Row rc  = load_row(xp, rbase,     c0, col, lane);
    Row rn  = load_row(xp, rbase + 1, c0, col, lane);
    Row rn2 = load_row(xp, rbase + 2, c0, col, lane);

    float4 hsA = hsum(rm, lane);
    float4 hsB = hsum(rc, lane);
    float4 vc  = rc.v;

    float* op = yp + rbase * W + col;

    #pragma unroll 4
    for (int i = 0; i < ROWS; i++) {
        Row rn3 = load_row(xp, rbase + i + 3, c0, col, lane);  // prefetch d=2
        float4 hsC = hsum(rn, lane);

        float4 o;
        o.x = fabsf(0.125f * (hsA.x + hsB.x + hsC.x) - 1.125f * vc.x) + 1e-5f;
        o.y = fabsf(0.125f * (hsA.y + hsB.y + hsC.y) - 1.125f * vc.y) + 1e-5f;
        o.z = fabsf(0.125f * (hsA.z + hsB.z + hsC.z) - 1.125f * vc.z) + 1e-5f;
        o.w = fabsf(0.125f * (hsA.w + hsB.w + hsC.w) - 1.125f * vc.w) + 1e-5f;

        __stcs(reinterpret_cast<float4*>(op), o);   // streaming store: no reuse
        op += W;

        hsA = hsB; hsB = hsC; vc = rn.v; rn = rn2; rn2 = rn3;
    }
}

extern "C" void kernel_launch(void* const* d_in, const int* in_sizes, int n_in,
                              void* d_out, int out_size) {
    const float* x = (const float*)d_in[0];
    float* y = (float*)d_out;

    const int planes = out_size / (W * H);           // 256
    dim3 block(256, 1, 1);
    dim3 grid(W / TW, H / (ROWS * WARPS), planes);   // (4, 4, 256) = 4096 CTAs
    highpass_kernel<<<grid, block>>>(x, y);
}